// round 14
// baseline (speedup 1.0000x reference)
#include <cuda_runtime.h>

#define Lc 2048
#define Bc 2048
#define NSEG 47          // grid = 47*16 = 752 -> 5 resident blocks on 148 of 148 SMs
#define WUP 4            // warmup steps = exactly one PD-group
#define PD 4             // steps per staged group
#define NBUF 2           // em smem ring buffers (prefetch distance 1 group)
#define MAXSTEP 48       // packed steps per thread (48 max; stride 48 = 0 mod 4)

typedef unsigned int u32;
typedef unsigned long long u64;

// ---------------- device scratch ----------------
__device__ float g_G [NSEG*Bc];
__device__ float g_sc[NSEG*Bc];
__device__ int   g_ct[NSEG*Bc];
__device__ float g_fin[Bc];
__device__ float g_part[16];

__device__ __forceinline__ void cp16(u32 dst, const void* src) {
    asm volatile("cp.async.cg.shared.global [%0], [%1], 16;" :: "r"(dst), "l"(src));
}
__device__ __forceinline__ void cp_commit() { asm volatile("cp.async.commit_group;"); }
__device__ __forceinline__ void cp_wait1()  { asm volatile("cp.async.wait_group 1;"); }

__device__ __forceinline__ u64 pk2(float lo, float hi) {
    u64 r; asm("mov.b64 %0, {%1, %2};" : "=l"(r) : "f"(lo), "f"(hi)); return r;
}
__device__ __forceinline__ void upk2(float& lo, float& hi, u64 v) {
    asm("mov.b64 {%0, %1}, %2;" : "=f"(lo), "=f"(hi) : "l"(v));
}
__device__ __forceinline__ u64 fma2(u64 a, u64 b, u64 c) {
    u64 d; asm("fma.rn.f32x2 %0, %1, %2, %3;" : "=l"(d) : "l"(a), "l"(b), "l"(c)); return d;
}
__device__ __forceinline__ u64 mul2(u64 a, u64 b) {
    u64 d; asm("mul.rn.f32x2 %0, %1, %2;" : "=l"(d) : "l"(a), "l"(b)); return d;
}

// ---------------- main segmented scan ----------------
// 752 blocks x 128 threads; s = blockIdx>>4, 16 blocks/segment, thread = (chain b, seg s).
__global__ __launch_bounds__(128, 5) void crf_seg(
    const float* __restrict__ em,    const int* __restrict__ tags,
    const int*   __restrict__ qmask, const int* __restrict__ mask,
    const float* __restrict__ startT, const float* __restrict__ endT,
    const float* __restrict__ selfT,  const float* __restrict__ otherT)
{
    __shared__ float shS[49], shO[49], shEO[49];
    __shared__ float4 sEm4[4][NBUF*224];            // per-warp em ring: 2 bufs x (4 steps x 224 floats)
    __shared__ unsigned char sPk[128][MAXSTEP];     // per-thread packed step bytes
    for (int k = threadIdx.x; k < 49; k += 128) {
        float o = otherT[k];
        shS[k] = selfT[k]; shO[k] = o; shEO[k] = __expf(o);
    }
    __syncthreads();

    const int tid  = threadIdx.x;
    const int wid  = tid >> 5, lane = tid & 31;
    const int s    = blockIdx.x >> 4;
    const int b    = ((blockIdx.x & 15) << 7) + tid;
    const int b0   = ((blockIdx.x & 15) << 7) + (wid << 5);   // warp's base chain
    float4* sd = sEm4[wid];
    const float* sEbase = (const float*)sd;
    const int sOfs = 7 * lane;
    // cp.async mapping: thread covers step-row r = lane>>3, chunk c = lane&7 (7 float4s)
    const int cprow = lane >> 3, cpc = (lane & 7) * 7;
    const u32 sdAddr = (u32)__cvta_generic_to_shared(sd);

    // exp(self) matrix packed over j-pairs: Ep01[i]=(E[i][0],E[i][1]) etc; j=6 scalar
    u64 Ep01[7], Ep23[7], Ep45[7]; float Ep6[7];
#pragma unroll
    for (int i = 0; i < 7; i++) {
        Ep01[i] = pk2(__expf(selfT[i*7+0]), __expf(selfT[i*7+1]));
        Ep23[i] = pk2(__expf(selfT[i*7+2]), __expf(selfT[i*7+3]));
        Ep45[i] = pk2(__expf(selfT[i*7+4]), __expf(selfT[i*7+5]));
        Ep6[i]  = __expf(selfT[i*7+6]);
    }

    // segment bounds: owned transitions l in (startl, lend]
    const int startl = (s * Lc) / NSEG;                       // 0 for s=0
    const int lend0  = ((s + 1) * Lc) / NSEG;
    const int lend   = (lend0 > Lc - 1) ? (Lc - 1) : lend0;   // only s=46 clamps
    const int lstart = (s == 0) ? 1 : (startl - WUP + 1);
    const int ngrp   = (lend0 - lstart + 1 + PD - 1) / PD;    // 11 (s=0) or 12
    const int nstep  = ngrp * PD;
    const int resetg = (s == 0) ? -1 : 0;                     // warmup = group 0 exactly

    // ---- cp.async prologue: em groups 0 and 1 into slots 0,1 ----
#pragma unroll
    for (int pg = 0; pg < 2; pg++) {
        int l = lstart + pg * PD + cprow; l = (l > Lc - 1) ? (Lc - 1) : l;
        const float4* src = (const float4*)(em + ((size_t)l * Bc + b0) * 7) + cpc;
        u32 dst = sdAddr + (u32)(pg * 224 + cprow * 56 + cpc) * 16u;
#pragma unroll
        for (int i = 0; i < 7; i++) cp16(dst + i * 16u, src + i);
        cp_commit();
    }

    // ---- int pre-pass: pack (tag, mk, cont, scoreable) bytes; trans-score; cnt ----
    float score; int cnt;
    if (s == 0) {
        const float* e0 = em + (size_t)b * 7;
        const int tg0 = tags[b];
        float et = e0[0];
#pragma unroll
        for (int j = 1; j < 7; j++) et = (tg0 == j) ? e0[j] : et;
        score = startT[tg0] + et;
        cnt = mask[b];
    } else {
        score = 0.f; cnt = 0;
    }
    {
        int pb = (lstart - 1) * Bc + b;
        int qprev = qmask[pb], tgprev = tags[pb];
#pragma unroll 4
        for (int i = 0; i < nstep; i++) {
            const int l = lstart + i;
            const int lc = (l > Lc - 1) ? (Lc - 1) : l;
            const int bb = lc * Bc + b;
            const int mkr = mask[bb], q = qmask[bb], tg = tags[bb];
            const int valid = (l <= lend);
            const int mk = valid ? mkr : 0;
            const int cont = (q != qprev) ? 1 : 0;
            const int scb = (l > startl) && mk;               // owned & masked
            if (scb) {
                score += (cont ? shO : shS)[tgprev * 7 + tg];
                cnt++;
            }
            sPk[tid][i] = (unsigned char)(tg | (mk << 3) | (cont << 4) | (scb << 5));
            if (mk) { qprev = q; tgprev = tg; }
        }
    }

    // ---- hot scan loop ----
    float w[7], C;
    if (s == 0) {
        const float* e0 = em + (size_t)b * 7;
        float a[7]; float m = -1e30f;
#pragma unroll
        for (int j = 0; j < 7; j++) { a[j] = startT[j] + e0[j]; m = fmaxf(m, a[j]); }
#pragma unroll
        for (int j = 0; j < 7; j++) w[j] = __expf(a[j] - m);
        C = m;
    } else {
#pragma unroll
        for (int j = 0; j < 7; j++) w[j] = 1.0f;
        C = 0.f;
    }

#pragma unroll 1
    for (int g = 0; g < ngrp; g++) {
        cp_wait1();                     // group g complete (group g+1 may be in flight)
        __syncwarp();

        const int slot = g & 1;
        const float* sE = sEbase + slot * 896;
        const u32 pk4 = *(const u32*)(&sPk[tid][g * 4]);

        // ---- 4 steps from smem ----
#pragma unroll
        for (int k = 0; k < PD; k++) {
            const u32 byte = (pk4 >> (8 * k)) & 0xFFu;
            const bool cont = (byte & 0x10u) != 0u;
            const bool mk   = (byte & 0x08u) != 0u;
            const float* xr = sE + k * 224 + sOfs;

            if (mk) {
                if (!cont) {
                    // packed f32x2 matvec over j-pairs
                    u64 wd = pk2(w[0], w[0]);
                    u64 s01 = mul2(wd, Ep01[0]);
                    u64 s23 = mul2(wd, Ep23[0]);
                    u64 s45 = mul2(wd, Ep45[0]);
                    float s6 = w[0] * Ep6[0];
#pragma unroll
                    for (int i = 1; i < 7; i++) {
                        wd  = pk2(w[i], w[i]);
                        s01 = fma2(wd, Ep01[i], s01);
                        s23 = fma2(wd, Ep23[i], s23);
                        s45 = fma2(wd, Ep45[i], s45);
                        s6  = fmaf(w[i], Ep6[i], s6);
                    }
                    const float e0 = __expf(xr[0]), e1 = __expf(xr[1]);
                    const float e2 = __expf(xr[2]), e3 = __expf(xr[3]);
                    const float e4 = __expf(xr[4]), e5 = __expf(xr[5]);
                    const float e6 = __expf(xr[6]);
                    s01 = mul2(s01, pk2(e0, e1));
                    s23 = mul2(s23, pk2(e2, e3));
                    s45 = mul2(s45, pk2(e4, e5));
                    upk2(w[0], w[1], s01);
                    upk2(w[2], w[3], s23);
                    upk2(w[4], w[5], s45);
                    w[6] = s6 * e6;
                } else {
                    // rare path: other_transitions matrix from shared (scalar)
                    float sv[7];
#pragma unroll
                    for (int j = 0; j < 7; j++) sv[j] = w[0] * shEO[j];
#pragma unroll
                    for (int i = 1; i < 7; i++)
#pragma unroll
                        for (int j = 0; j < 7; j++) sv[j] = fmaf(w[i], shEO[i * 7 + j], sv[j]);
#pragma unroll
                    for (int j = 0; j < 7; j++) w[j] = sv[j] * __expf(xr[j]);
                }
                if (byte & 0x20u) {                    // owned & masked: em part of score
                    score += xr[byte & 7u];
                }
            }
        }
        __syncwarp();                   // all lanes done reading em slot before refill

        // issue cp.async for em group g+2 into the slot just freed (slot g&1)
        if (g + 2 < ngrp) {
            int l = lstart + (g + 2) * PD + cprow; l = (l > Lc - 1) ? (Lc - 1) : l;
            const float4* src = (const float4*)(em + ((size_t)l * Bc + b0) * 7) + cpc;
            u32 dst = sdAddr + (u32)(slot * 224 + cprow * 56 + cpc) * 16u;
#pragma unroll
            for (int i = 0; i < 7; i++) cp16(dst + i * 16u, src + i);
        }
        cp_commit();                    // commit even when empty: keeps group count aligned

        if (g == resetg) {
            // warmup -> owned boundary: normalize direction, zero log-gain
            float m = w[0];
#pragma unroll
            for (int j = 1; j < 7; j++) m = fmaxf(m, w[j]);
            const float inv = 1.f / m;
#pragma unroll
            for (int j = 0; j < 7; j++) w[j] *= inv;
            C = 0.f;
        } else if (g & 1) {
            // renormalize every 8 steps
            float m = w[0];
#pragma unroll
            for (int j = 1; j < 7; j++) m = fmaxf(m, w[j]);
            C += __logf(m);
            const float inv = 1.f / m;
#pragma unroll
            for (int j = 0; j < 7; j++) w[j] *= inv;
        }
    }

    // finalize segment
    float m = w[0];
#pragma unroll
    for (int j = 1; j < 7; j++) m = fmaxf(m, w[j]);
    g_G [s * Bc + b] = C + __logf(m);
    g_sc[s * Bc + b] = score;
    g_ct[s * Bc + b] = cnt;
    if (s == NSEG - 1) {
        const float inv = 1.f / m;
        float sum = 0.f;
#pragma unroll
        for (int j = 0; j < 7; j++) sum += w[j] * inv * __expf(endT[j]);
        g_fin[b] = __logf(sum);
    }
}

// ---------------- per-chain combine + partial sums ----------------
__global__ void crf_fin(const int* __restrict__ tags,
                        const float* __restrict__ endT) {
    const int b = blockIdx.x * blockDim.x + threadIdx.x;   // 16 x 128 = 2048
    float G = 0.f, sc = 0.f; int ct = 0;
#pragma unroll
    for (int s = 0; s < NSEG; s++) {
        G  += g_G [s * Bc + b];
        sc += g_sc[s * Bc + b];
        ct += g_ct[s * Bc + b];
    }
    const float logZ = G + g_fin[b];
    const int tg_end = tags[(size_t)(ct - 1) * Bc + b];
    const float llh = sc + endT[tg_end] - logZ;

    __shared__ float red[128];
    red[threadIdx.x] = llh;
    __syncthreads();
    for (int off = 64; off > 0; off >>= 1) {
        if (threadIdx.x < off) red[threadIdx.x] += red[threadIdx.x + off];
        __syncthreads();
    }
    if (threadIdx.x == 0) g_part[blockIdx.x] = red[0];
}

__global__ void crf_fin2(float* __restrict__ out) {
    if (threadIdx.x == 0) {
        float s = 0.f;
        for (int k = 0; k < 16; k++) s += g_part[k];
        out[0] = s;
    }
}

// ---------------- launch ----------------
extern "C" void kernel_launch(void* const* d_in, const int* in_sizes, int n_in,
                              void* d_out, int out_size) {
    const float* em     = (const float*)d_in[0];
    const int*   tags   = (const int*)  d_in[1];
    const int*   qmask  = (const int*)  d_in[2];
    const int*   mask   = (const int*)  d_in[3];
    const float* startT = (const float*)d_in[4];
    const float* endT   = (const float*)d_in[5];
    const float* selfT  = (const float*)d_in[6];
    const float* otherT = (const float*)d_in[7];
    float* out = (float*)d_out;

    crf_seg<<<NSEG * 16, 128>>>(em, tags, qmask, mask, startT, endT, selfT, otherT);
    crf_fin<<<16, 128>>>(tags, endT);
    crf_fin2<<<1, 32>>>(out);
}

// round 15
// speedup vs baseline: 1.1316x; 1.1316x over previous
#include <cuda_runtime.h>

#define Lc 2048
#define Bc 2048
#define NSEG 37          // grid = 37*16 = 592 = 4 blocks x 148 SMs, single balanced wave
#define WUP 4            // warmup steps = exactly one PD-group
#define PD 4             // steps per staged group
#define NBUF 2           // em smem ring buffers
#define MAXSTEP 64       // packed steps per thread (60 used; 64 for stride padding)

typedef unsigned int u32;

// ---------------- device scratch ----------------
__device__ float g_G [NSEG*Bc];
__device__ float g_sc[NSEG*Bc];
__device__ int   g_ct[NSEG*Bc];
__device__ float g_fin[Bc];
__device__ float g_part[16];

__device__ __forceinline__ void cp16(u32 dst, const void* src) {
    asm volatile("cp.async.cg.shared.global [%0], [%1], 16;" :: "r"(dst), "l"(src));
}
__device__ __forceinline__ void cp_commit() { asm volatile("cp.async.commit_group;"); }
__device__ __forceinline__ void cp_wait1()  { asm volatile("cp.async.wait_group 1;"); }

// ---------------- main segmented scan ----------------
// 592 blocks x 128 threads; s = blockIdx>>4, 16 blocks/segment, thread = (chain b, seg s).
__global__ __launch_bounds__(128, 4) void crf_seg(
    const float* __restrict__ em,    const int* __restrict__ tags,
    const int*   __restrict__ qmask, const int* __restrict__ mask,
    const float* __restrict__ startT, const float* __restrict__ endT,
    const float* __restrict__ selfT,  const float* __restrict__ otherT)
{
    __shared__ float shS[49], shO[49], shEO[49];
    __shared__ float4 sEm4[4][NBUF*224];            // per-warp em ring: 2 bufs x (4 steps x 224 floats)
    __shared__ unsigned char sPk[128][MAXSTEP];     // per-thread packed step bytes
    for (int k = threadIdx.x; k < 49; k += 128) {
        float o = otherT[k];
        shS[k] = selfT[k]; shO[k] = o; shEO[k] = __expf(o);
    }
    __syncthreads();

    const int tid  = threadIdx.x;
    const int wid  = tid >> 5, lane = tid & 31;
    const int s    = blockIdx.x >> 4;
    const int b    = ((blockIdx.x & 15) << 7) + tid;
    const int b0   = ((blockIdx.x & 15) << 7) + (wid << 5);   // warp's base chain
    float4* sd = sEm4[wid];
    const float* sEbase = (const float*)sd;
    const int sOfs = 7 * lane;
    // cp.async mapping: thread covers step-row r = lane>>3, chunk c = lane&7 (7 float4s)
    const int cprow = lane >> 3, cpc = (lane & 7) * 7;
    const u32 sdAddr = (u32)__cvta_generic_to_shared(sd);

    // exp(self) matrix in registers (uniform broadcast loads)
    float Es[49];
#pragma unroll
    for (int k = 0; k < 49; k++) Es[k] = __expf(selfT[k]);

    // segment bounds: owned transitions l in (startl, lend]
    const int startl = (s * Lc) / NSEG;                       // 0 for s=0
    const int lend0  = ((s + 1) * Lc) / NSEG;
    const int lend   = (lend0 > Lc - 1) ? (Lc - 1) : lend0;   // only s=36 clamps
    const int lstart = (s == 0) ? 1 : (startl - WUP + 1);
    const int ngrp   = (lend0 - lstart + 1 + PD - 1) / PD;    // 14 (s=0) or 15
    const int nstep  = ngrp * PD;
    const int resetg = (s == 0) ? -1 : 0;                     // warmup = group 0 exactly

    // ---- cp.async prologue: em groups 0 and 1 into slots 0,1 ----
#pragma unroll
    for (int pg = 0; pg < 2; pg++) {
        int l = lstart + pg * PD + cprow; l = (l > Lc - 1) ? (Lc - 1) : l;
        const float4* src = (const float4*)(em + ((size_t)l * Bc + b0) * 7) + cpc;
        u32 dst = sdAddr + (u32)(pg * 224 + cprow * 56 + cpc) * 16u;
#pragma unroll
        for (int i = 0; i < 7; i++) cp16(dst + i * 16u, src + i);
        cp_commit();
    }

    // ---- int pre-pass: pack (tag, mk, cont, scoreable) bytes; trans-score; cnt ----
    float score; int cnt;
    if (s == 0) {
        const float* e0 = em + (size_t)b * 7;
        const int tg0 = tags[b];
        float et = e0[0];
#pragma unroll
        for (int j = 1; j < 7; j++) et = (tg0 == j) ? e0[j] : et;
        score = startT[tg0] + et;
        cnt = mask[b];
    } else {
        score = 0.f; cnt = 0;
    }
    {
        int pb = (lstart - 1) * Bc + b;
        int qprev = qmask[pb], tgprev = tags[pb];
#pragma unroll 4
        for (int i = 0; i < nstep; i++) {
            const int l = lstart + i;
            const int lc = (l > Lc - 1) ? (Lc - 1) : l;
            const int bb = lc * Bc + b;
            const int mkr = mask[bb], q = qmask[bb], tg = tags[bb];
            const int valid = (l <= lend);
            const int mk = valid ? mkr : 0;
            const int cont = (q != qprev) ? 1 : 0;
            const int scb = (l > startl) && mk;               // owned & masked
            if (scb) {
                score += (cont ? shO : shS)[tgprev * 7 + tg];
                cnt++;
            }
            sPk[tid][i] = (unsigned char)(tg | (mk << 3) | (cont << 4) | (scb << 5));
            if (mk) { qprev = q; tgprev = tg; }
        }
    }

    // ---- hot scan loop ----
    float w[7], C;
    if (s == 0) {
        const float* e0 = em + (size_t)b * 7;
        float a[7]; float m = -1e30f;
#pragma unroll
        for (int j = 0; j < 7; j++) { a[j] = startT[j] + e0[j]; m = fmaxf(m, a[j]); }
#pragma unroll
        for (int j = 0; j < 7; j++) w[j] = __expf(a[j] - m);
        C = m;
    } else {
#pragma unroll
        for (int j = 0; j < 7; j++) w[j] = 1.0f;
        C = 0.f;
    }

#pragma unroll 1
    for (int g = 0; g < ngrp; g++) {
        cp_wait1();                     // group g complete (group g+1 may be in flight)
        __syncwarp();

        const int slot = g & 1;
        const float* sE = sEbase + slot * 896;
        const u32 pk4 = *(const u32*)(&sPk[tid][g * 4]);

        // fast path: all 4 steps have mk=1 and cont=0 in EVERY lane of the warp
        const bool fastme = ((pk4 & 0x18181818u) == 0x08080808u);
        if (__ballot_sync(0xffffffffu, fastme) == 0xffffffffu) {
            // ---- branchless 4-step unroll ----
#pragma unroll
            for (int k = 0; k < PD; k++) {
                const u32 byte = (pk4 >> (8 * k)) & 0xFFu;
                const float* xr = sE + k * 224 + sOfs;
                float x[7], e[7];
#pragma unroll
                for (int j = 0; j < 7; j++) x[j] = xr[j];
#pragma unroll
                for (int j = 0; j < 7; j++) e[j] = __expf(x[j]);
                float sv[7];
#pragma unroll
                for (int j = 0; j < 7; j++) sv[j] = w[0] * Es[j];
#pragma unroll
                for (int i = 1; i < 7; i++)
#pragma unroll
                    for (int j = 0; j < 7; j++) sv[j] = fmaf(w[i], Es[i * 7 + j], sv[j]);
#pragma unroll
                for (int j = 0; j < 7; j++) w[j] = sv[j] * e[j];
                // score: add x[tag] iff scb bit (bit 5), branchlessly
                const float flag = (float)((byte >> 5) & 1u);
                score = fmaf(flag, xr[byte & 7u], score);
            }
        } else {
            // ---- general per-step path (warmup tails, masked, cont) ----
#pragma unroll
            for (int k = 0; k < PD; k++) {
                const u32 byte = (pk4 >> (8 * k)) & 0xFFu;
                const bool cont = (byte & 0x10u) != 0u;
                const bool mk   = (byte & 0x08u) != 0u;
                const float* xr = sE + k * 224 + sOfs;
                float x[7], e[7];
#pragma unroll
                for (int j = 0; j < 7; j++) x[j] = xr[j];
#pragma unroll
                for (int j = 0; j < 7; j++) e[j] = __expf(x[j]);
                float sv[7];
                if (!cont) {
#pragma unroll
                    for (int j = 0; j < 7; j++) sv[j] = w[0] * Es[j];
#pragma unroll
                    for (int i = 1; i < 7; i++)
#pragma unroll
                        for (int j = 0; j < 7; j++) sv[j] = fmaf(w[i], Es[i * 7 + j], sv[j]);
                } else {
#pragma unroll
                    for (int j = 0; j < 7; j++) sv[j] = w[0] * shEO[j];
#pragma unroll
                    for (int i = 1; i < 7; i++)
#pragma unroll
                        for (int j = 0; j < 7; j++) sv[j] = fmaf(w[i], shEO[i * 7 + j], sv[j]);
                }
                if (mk) {
#pragma unroll
                    for (int j = 0; j < 7; j++) w[j] = sv[j] * e[j];
                }
                if (byte & 0x20u) {
                    score += xr[byte & 7u];
                }
            }
        }
        __syncwarp();                   // all lanes done reading em slot before refill

        // issue cp.async for em group g+2 into the slot just freed (slot g&1)
        if (g + 2 < ngrp) {
            int l = lstart + (g + 2) * PD + cprow; l = (l > Lc - 1) ? (Lc - 1) : l;
            const float4* src = (const float4*)(em + ((size_t)l * Bc + b0) * 7) + cpc;
            u32 dst = sdAddr + (u32)(slot * 224 + cprow * 56 + cpc) * 16u;
#pragma unroll
            for (int i = 0; i < 7; i++) cp16(dst + i * 16u, src + i);
        }
        cp_commit();                    // commit even when empty: keeps group count aligned

        if (g == resetg) {
            // warmup -> owned boundary: normalize direction, zero log-gain
            float m = w[0];
#pragma unroll
            for (int j = 1; j < 7; j++) m = fmaxf(m, w[j]);
            const float inv = 1.f / m;
#pragma unroll
            for (int j = 0; j < 7; j++) w[j] *= inv;
            C = 0.f;
        } else if (g & 1) {
            // renormalize every 8 steps
            float m = w[0];
#pragma unroll
            for (int j = 1; j < 7; j++) m = fmaxf(m, w[j]);
            C += __logf(m);
            const float inv = 1.f / m;
#pragma unroll
            for (int j = 0; j < 7; j++) w[j] *= inv;
        }
    }

    // finalize segment
    float m = w[0];
#pragma unroll
    for (int j = 1; j < 7; j++) m = fmaxf(m, w[j]);
    g_G [s * Bc + b] = C + __logf(m);
    g_sc[s * Bc + b] = score;
    g_ct[s * Bc + b] = cnt;
    if (s == NSEG - 1) {
        const float inv = 1.f / m;
        float sum = 0.f;
#pragma unroll
        for (int j = 0; j < 7; j++) sum += w[j] * inv * __expf(endT[j]);
        g_fin[b] = __logf(sum);
    }
}

// ---------------- per-chain combine + partial sums ----------------
__global__ void crf_fin(const int* __restrict__ tags,
                        const float* __restrict__ endT) {
    const int b = blockIdx.x * blockDim.x + threadIdx.x;   // 16 x 128 = 2048
    float G = 0.f, sc = 0.f; int ct = 0;
#pragma unroll
    for (int s = 0; s < NSEG; s++) {
        G  += g_G [s * Bc + b];
        sc += g_sc[s * Bc + b];
        ct += g_ct[s * Bc + b];
    }
    const float logZ = G + g_fin[b];
    const int tg_end = tags[(size_t)(ct - 1) * Bc + b];
    const float llh = sc + endT[tg_end] - logZ;

    __shared__ float red[128];
    red[threadIdx.x] = llh;
    __syncthreads();
    for (int off = 64; off > 0; off >>= 1) {
        if (threadIdx.x < off) red[threadIdx.x] += red[threadIdx.x + off];
        __syncthreads();
    }
    if (threadIdx.x == 0) g_part[blockIdx.x] = red[0];
}

__global__ void crf_fin2(float* __restrict__ out) {
    if (threadIdx.x == 0) {
        float s = 0.f;
        for (int k = 0; k < 16; k++) s += g_part[k];
        out[0] = s;
    }
}

// ---------------- launch ----------------
extern "C" void kernel_launch(void* const* d_in, const int* in_sizes, int n_in,
                              void* d_out, int out_size) {
    const float* em     = (const float*)d_in[0];
    const int*   tags   = (const int*)  d_in[1];
    const int*   qmask  = (const int*)  d_in[2];
    const int*   mask   = (const int*)  d_in[3];
    const float* startT = (const float*)d_in[4];
    const float* endT   = (const float*)d_in[5];
    const float* selfT  = (const float*)d_in[6];
    const float* otherT = (const float*)d_in[7];
    float* out = (float*)d_out;

    crf_seg<<<NSEG * 16, 128>>>(em, tags, qmask, mask, startT, endT, selfT, otherT);
    crf_fin<<<16, 128>>>(tags, endT);
    crf_fin2<<<1, 32>>>(out);
}

// round 17
// speedup vs baseline: 1.1693x; 1.0333x over previous
#include <cuda_runtime.h>

#define Lc 2048
#define Bc 2048
#define NSEG 37          // grid = 37*16 = 592 = 4 blocks x 148 SMs, single balanced wave
#define WUP 4            // warmup steps = exactly two PD-groups
#define PD 2             // steps per staged group
#define NBUF 5           // em smem ring buffers; up to 3 groups in flight
#define MAXSTEP 64       // packed steps per thread (60 used; 64 for stride padding)
#define GF4 112          // float4s per group: 2 steps x 56

typedef unsigned int u32;
typedef unsigned short u16;

// ---------------- device scratch ----------------
__device__ float g_G [NSEG*Bc];
__device__ float g_sc[NSEG*Bc];
__device__ int   g_ct[NSEG*Bc];
__device__ float g_fin[Bc];
__device__ float g_part[16];

__device__ __forceinline__ void cp16(u32 dst, const void* src) {
    asm volatile("cp.async.cg.shared.global [%0], [%1], 16;" :: "r"(dst), "l"(src));
}
__device__ __forceinline__ void cp_commit() { asm volatile("cp.async.commit_group;"); }
__device__ __forceinline__ void cp_wait3()  { asm volatile("cp.async.wait_group 3;"); }

// ---------------- main segmented scan ----------------
// 592 blocks x 128 threads; s = blockIdx>>4, 16 blocks/segment, thread = (chain b, seg s).
__global__ __launch_bounds__(128, 4) void crf_seg(
    const float* __restrict__ em,    const int* __restrict__ tags,
    const int*   __restrict__ qmask, const int* __restrict__ mask,
    const float* __restrict__ startT, const float* __restrict__ endT,
    const float* __restrict__ selfT,  const float* __restrict__ otherT)
{
    __shared__ float shS[49], shO[49], shEO[49];
    __shared__ float4 sEm4[4][NBUF*GF4];            // per-warp em ring: 5 bufs x (2 steps x 224 floats)
    __shared__ unsigned char sPk[128][MAXSTEP];     // per-thread packed step bytes
    for (int k = threadIdx.x; k < 49; k += 128) {
        float o = otherT[k];
        shS[k] = selfT[k]; shO[k] = o; shEO[k] = __expf(o);
    }
    __syncthreads();

    const int tid  = threadIdx.x;
    const int wid  = tid >> 5, lane = tid & 31;
    const int s    = blockIdx.x >> 4;
    const int b    = ((blockIdx.x & 15) << 7) + tid;
    const int b0   = ((blockIdx.x & 15) << 7) + (wid << 5);   // warp's base chain
    float4* sd = sEm4[wid];
    const float* sEbase = (const float*)sd;
    const int sOfs = 7 * lane;
    const u32 sdAddr = (u32)__cvta_generic_to_shared(sd);

    // cp.async mapping: lanes 0..27 each move 4 float4s of the 112-float4 group
    int lrowA[4], f4oA[4], vldA[4];
#pragma unroll
    for (int i = 0; i < 4; i++) {
        const int idx = lane * 4 + i;
        vldA[i]  = (idx < GF4);
        lrowA[i] = (idx < 56) ? 0 : 1;
        f4oA[i]  = idx - lrowA[i] * 56;
    }

    // exp(self) matrix in registers (uniform broadcast loads)
    float Es[49];
#pragma unroll
    for (int k = 0; k < 49; k++) Es[k] = __expf(selfT[k]);

    // segment bounds: owned transitions l in (startl, lend]
    const int startl = (s * Lc) / NSEG;                       // 0 for s=0
    const int lend0  = ((s + 1) * Lc) / NSEG;
    const int lend   = (lend0 > Lc - 1) ? (Lc - 1) : lend0;   // only s=36 clamps
    const int lstart = (s == 0) ? 1 : (startl - WUP + 1);
    const int ngrp   = (lend0 - lstart + 1 + PD - 1) / PD;    // 28 (s=0) or 30
    const int nstep  = ngrp * PD;
    const int resetg = (s == 0) ? -1 : 1;                     // warmup = groups 0,1

    // ---- cp.async prologue: groups 0..3 into slots 0..3 ----
#pragma unroll
    for (int pg = 0; pg < 4; pg++) {
        const int lbase = lstart + pg * PD;
#pragma unroll
        for (int i = 0; i < 4; i++) {
            if (vldA[i]) {
                const int l = min(lbase + lrowA[i], Lc - 1);
                const float4* src = (const float4*)(em + ((size_t)l * Bc + b0) * 7) + f4oA[i];
                cp16(sdAddr + (u32)(pg * GF4 + lane * 4 + i) * 16u, src);
            }
        }
        cp_commit();
    }

    // ---- int pre-pass: pack (tag, mk, cont, scoreable) bytes; trans-score; cnt ----
    float score; int cnt;
    if (s == 0) {
        const float* e0 = em + (size_t)b * 7;
        const int tg0 = tags[b];
        float et = e0[0];
#pragma unroll
        for (int j = 1; j < 7; j++) et = (tg0 == j) ? e0[j] : et;
        score = startT[tg0] + et;
        cnt = mask[b];
    } else {
        score = 0.f; cnt = 0;
    }
    {
        int pb = (lstart - 1) * Bc + b;
        int qprev = qmask[pb], tgprev = tags[pb];
#pragma unroll 4
        for (int i = 0; i < nstep; i++) {
            const int l = lstart + i;
            const int lc = (l > Lc - 1) ? (Lc - 1) : l;
            const int bb = lc * Bc + b;
            const int mkr = mask[bb], q = qmask[bb], tg = tags[bb];
            const int valid = (l <= lend);
            const int mk = valid ? mkr : 0;
            const int cont = (q != qprev) ? 1 : 0;
            const int scb = (l > startl) && mk;               // owned & masked
            if (scb) {
                score += (cont ? shO : shS)[tgprev * 7 + tg];
                cnt++;
            }
            sPk[tid][i] = (unsigned char)(tg | (mk << 3) | (cont << 4) | (scb << 5));
            if (mk) { qprev = q; tgprev = tg; }
        }
    }

    // ---- hot scan loop ----
    float w[7], C;
    if (s == 0) {
        const float* e0 = em + (size_t)b * 7;
        float a[7]; float m = -1e30f;
#pragma unroll
        for (int j = 0; j < 7; j++) { a[j] = startT[j] + e0[j]; m = fmaxf(m, a[j]); }
#pragma unroll
        for (int j = 0; j < 7; j++) w[j] = __expf(a[j] - m);
        C = m;
    } else {
#pragma unroll
        for (int j = 0; j < 7; j++) w[j] = 1.0f;
        C = 0.f;
    }

    int slot = 0;
#pragma unroll 1
    for (int g = 0; g < ngrp; g++) {
        cp_wait3();                     // group g complete (up to 3 newer pending)
        __syncwarp();

        const float* sE = sEbase + slot * (GF4 * 4);
        const u32 pk2 = *(const u16*)(&sPk[tid][g * 2]);

        // fast path: both steps have mk=1, cont=0 in EVERY lane of the warp
        const bool fastme = ((pk2 & 0x1818u) == 0x0808u);
        if (__ballot_sync(0xffffffffu, fastme) == 0xffffffffu) {
#pragma unroll
            for (int k = 0; k < PD; k++) {
                const u32 byte = (pk2 >> (8 * k)) & 0xFFu;
                const float* xr = sE + k * 224 + sOfs;
                float e[7];
#pragma unroll
                for (int j = 0; j < 7; j++) e[j] = __expf(xr[j]);
                float sv[7];
#pragma unroll
                for (int j = 0; j < 7; j++) sv[j] = w[0] * Es[j];
#pragma unroll
                for (int i = 1; i < 7; i++)
#pragma unroll
                    for (int j = 0; j < 7; j++) sv[j] = fmaf(w[i], Es[i * 7 + j], sv[j]);
#pragma unroll
                for (int j = 0; j < 7; j++) w[j] = sv[j] * e[j];
                const float flag = (float)((byte >> 5) & 1u);
                score = fmaf(flag, xr[byte & 7u], score);
            }
        } else {
            // general per-step path (warmup tails, masked, cont)
#pragma unroll
            for (int k = 0; k < PD; k++) {
                const u32 byte = (pk2 >> (8 * k)) & 0xFFu;
                const bool cont = (byte & 0x10u) != 0u;
                const bool mk   = (byte & 0x08u) != 0u;
                const float* xr = sE + k * 224 + sOfs;
                float e[7];
#pragma unroll
                for (int j = 0; j < 7; j++) e[j] = __expf(xr[j]);
                float sv[7];
                if (!cont) {
#pragma unroll
                    for (int j = 0; j < 7; j++) sv[j] = w[0] * Es[j];
#pragma unroll
                    for (int i = 1; i < 7; i++)
#pragma unroll
                        for (int j = 0; j < 7; j++) sv[j] = fmaf(w[i], Es[i * 7 + j], sv[j]);
                } else {
#pragma unroll
                    for (int j = 0; j < 7; j++) sv[j] = w[0] * shEO[j];
#pragma unroll
                    for (int i = 1; i < 7; i++)
#pragma unroll
                        for (int j = 0; j < 7; j++) sv[j] = fmaf(w[i], shEO[i * 7 + j], sv[j]);
                }
                if (mk) {
#pragma unroll
                    for (int j = 0; j < 7; j++) w[j] = sv[j] * e[j];
                }
                if (byte & 0x20u) {
                    score += xr[byte & 7u];
                }
            }
        }
        __syncwarp();                   // all lanes done reading em slot before refill

        // issue cp.async for group g+4 into the slot freed at iteration g-1
        if (g + 4 < ngrp) {
            const int slot4 = (slot + 4 >= NBUF) ? (slot + 4 - NBUF) : (slot + 4);
            const int lbase = lstart + (g + 4) * PD;
#pragma unroll
            for (int i = 0; i < 4; i++) {
                if (vldA[i]) {
                    const int l = min(lbase + lrowA[i], Lc - 1);
                    const float4* src = (const float4*)(em + ((size_t)l * Bc + b0) * 7) + f4oA[i];
                    cp16(sdAddr + (u32)(slot4 * GF4 + lane * 4 + i) * 16u, src);
                }
            }
        }
        cp_commit();                    // commit even when empty: keeps group count aligned

        if (g == resetg) {
            // warmup -> owned boundary: normalize direction, zero log-gain
            float m = w[0];
#pragma unroll
            for (int j = 1; j < 7; j++) m = fmaxf(m, w[j]);
            const float inv = 1.f / m;
#pragma unroll
            for (int j = 0; j < 7; j++) w[j] *= inv;
            C = 0.f;
        } else if ((g & 3) == 3) {
            // renormalize every 8 steps
            float m = w[0];
#pragma unroll
            for (int j = 1; j < 7; j++) m = fmaxf(m, w[j]);
            C += __logf(m);
            const float inv = 1.f / m;
#pragma unroll
            for (int j = 0; j < 7; j++) w[j] *= inv;
        }

        slot = (slot + 1 >= NBUF) ? 0 : (slot + 1);
    }

    // finalize segment
    float m = w[0];
#pragma unroll
    for (int j = 1; j < 7; j++) m = fmaxf(m, w[j]);
    g_G [s * Bc + b] = C + __logf(m);
    g_sc[s * Bc + b] = score;
    g_ct[s * Bc + b] = cnt;
    if (s == NSEG - 1) {
        const float inv = 1.f / m;
        float sum = 0.f;
#pragma unroll
        for (int j = 0; j < 7; j++) sum += w[j] * inv * __expf(endT[j]);
        g_fin[b] = __logf(sum);
    }
}

// ---------------- per-chain combine + partial sums ----------------
__global__ void crf_fin(const int* __restrict__ tags,
                        const float* __restrict__ endT) {
    const int b = blockIdx.x * blockDim.x + threadIdx.x;   // 16 x 128 = 2048
    float G = 0.f, sc = 0.f; int ct = 0;
#pragma unroll
    for (int s = 0; s < NSEG; s++) {
        G  += g_G [s * Bc + b];
        sc += g_sc[s * Bc + b];
        ct += g_ct[s * Bc + b];
    }
    const float logZ = G + g_fin[b];
    const int tg_end = tags[(size_t)(ct - 1) * Bc + b];
    const float llh = sc + endT[tg_end] - logZ;

    __shared__ float red[128];
    red[threadIdx.x] = llh;
    __syncthreads();
    for (int off = 64; off > 0; off >>= 1) {
        if (threadIdx.x < off) red[threadIdx.x] += red[threadIdx.x + off];
        __syncthreads();
    }
    if (threadIdx.x == 0) g_part[blockIdx.x] = red[0];
}

__global__ void crf_fin2(float* __restrict__ out) {
    if (threadIdx.x == 0) {
        float s = 0.f;
        for (int k = 0; k < 16; k++) s += g_part[k];
        out[0] = s;
    }
}

// ---------------- launch ----------------
extern "C" void kernel_launch(void* const* d_in, const int* in_sizes, int n_in,
                              void* d_out, int out_size) {
    const float* em     = (const float*)d_in[0];
    const int*   tags   = (const int*)  d_in[1];
    const int*   qmask  = (const int*)  d_in[2];
    const int*   mask   = (const int*)  d_in[3];
    const float* startT = (const float*)d_in[4];
    const float* endT   = (const float*)d_in[5];
    const float* selfT  = (const float*)d_in[6];
    const float* otherT = (const float*)d_in[7];
    float* out = (float*)d_out;

    crf_seg<<<NSEG * 16, 128>>>(em, tags, qmask, mask, startT, endT, selfT, otherT);
    crf_fin<<<16, 128>>>(tags, endT);
    crf_fin2<<<1, 32>>>(out);
}